// round 1
// baseline (speedup 1.0000x reference)
#include <cuda_runtime.h>
#include <math.h>

#define T_SEQ 2048
#define HID 4096
#define NH 32
#define NKV 8
#define HD 128
#define GRP 4   // query heads per kv head

// Scratch (allocation-free rule: __device__ globals)
__device__ float g_Q[(size_t)T_SEQ * NH * HD];          // 32 MB
__device__ float g_K[(size_t)T_SEQ * NKV * HD];         // 8 MB
__device__ float g_V[(size_t)T_SEQ * NKV * HD];         // 8 MB
__device__ float g_S[(size_t)NH * T_SEQ * T_SEQ];       // 512 MB
__device__ float g_O[(size_t)T_SEQ * NH * HD];          // 32 MB

// ---------------------------------------------------------------------------
// Tiled SGEMM: C[M,N] = A[M,K] * op(B)
//   BT=true : B is [N,K] row-major (C = A * B^T)
//   BT=false: B is [K,N] row-major (C = A * B)
// Block tile 128x128, K-step 8, 256 threads, 8x8 per-thread micro-tile.
// Batched via blockIdx.z: Aoff = z*sA, Boff = (z/gdiv)*sB, Coff = z*sC.
// Requires: M,N % 128 == 0, K % 8 == 0, 16B-aligned tile starts.
// ---------------------------------------------------------------------------
template <bool BT>
__global__ __launch_bounds__(256)
void gemm128(const float* __restrict__ A, const float* __restrict__ B,
             float* __restrict__ C,
             int M, int N, int K, int lda, int ldb, int ldc,
             long sA, long sB, long sC, int gdiv)
{
    __shared__ float As[8][128];
    __shared__ float Bs[8][128];

    const int z = blockIdx.z;
    A += (long)z * sA;
    B += (long)(z / gdiv) * sB;
    C += (long)z * sC;

    const int bm = blockIdx.y * 128;
    const int bn = blockIdx.x * 128;
    const int tid = threadIdx.x;
    const int tx = tid & 15;        // 0..15 -> N micro-tile
    const int ty = tid >> 4;        // 0..15 -> M micro-tile

    float acc[8][8];
    #pragma unroll
    for (int i = 0; i < 8; i++)
        #pragma unroll
        for (int j = 0; j < 8; j++) acc[i][j] = 0.0f;

    for (int k0 = 0; k0 < K; k0 += 8) {
        // Load A tile (128 rows x 8 k), transposed into As[k][m]
        {
            const int r = tid >> 1;
            const int c4 = (tid & 1) * 4;
            float4 a = *reinterpret_cast<const float4*>(A + (long)(bm + r) * lda + k0 + c4);
            As[c4 + 0][r] = a.x; As[c4 + 1][r] = a.y;
            As[c4 + 2][r] = a.z; As[c4 + 3][r] = a.w;
        }
        if (BT) {
            // B is [N,K]: load 128 n-rows x 8 k, into Bs[k][n]
            const int r = tid >> 1;
            const int c4 = (tid & 1) * 4;
            float4 b = *reinterpret_cast<const float4*>(B + (long)(bn + r) * ldb + k0 + c4);
            Bs[c4 + 0][r] = b.x; Bs[c4 + 1][r] = b.y;
            Bs[c4 + 2][r] = b.z; Bs[c4 + 3][r] = b.w;
        } else {
            // B is [K,N]: load 8 k-rows x 128 n, into Bs[k][n]
            const int kk = tid >> 5;
            const int c = (tid & 31) * 4;
            float4 b = *reinterpret_cast<const float4*>(B + (long)(k0 + kk) * ldb + bn + c);
            *reinterpret_cast<float4*>(&Bs[kk][c]) = b;
        }
        __syncthreads();

        #pragma unroll
        for (int k = 0; k < 8; k++) {
            float a[8], b[8];
            *reinterpret_cast<float4*>(a)     = *reinterpret_cast<float4*>(&As[k][ty * 8]);
            *reinterpret_cast<float4*>(a + 4) = *reinterpret_cast<float4*>(&As[k][ty * 8 + 4]);
            *reinterpret_cast<float4*>(b)     = *reinterpret_cast<float4*>(&Bs[k][tx * 8]);
            *reinterpret_cast<float4*>(b + 4) = *reinterpret_cast<float4*>(&Bs[k][tx * 8 + 4]);
            #pragma unroll
            for (int i = 0; i < 8; i++)
                #pragma unroll
                for (int j = 0; j < 8; j++)
                    acc[i][j] = fmaf(a[i], b[j], acc[i][j]);
        }
        __syncthreads();
    }

    #pragma unroll
    for (int i = 0; i < 8; i++) {
        float* crow = C + (long)(bm + ty * 8 + i) * ldc + bn + tx * 8;
        #pragma unroll
        for (int j = 0; j < 8; j += 4) {
            float4 v = make_float4(acc[i][j], acc[i][j + 1], acc[i][j + 2], acc[i][j + 3]);
            *reinterpret_cast<float4*>(crow + j) = v;
        }
    }
}

// ---------------------------------------------------------------------------
// Llama-3 RoPE applied in place to [T, heads*128] (head-major columns).
// grid = (T, heads), block = 64 threads (one per rotation pair).
// ---------------------------------------------------------------------------
__global__ void rope_kernel(float* __restrict__ q, int heads)
{
    const int t = blockIdx.x;
    const int h = blockIdx.y;
    const int i = threadIdx.x;   // 0..63

    // inv_freq (llama3 scaling), computed in double for stability
    double invd = exp(-((double)(2 * i) / 128.0) * log(500000.0));
    float inv = (float)invd;
    float wavelen = (float)(2.0 * 3.14159265358979323846 / invd);
    float inv_scaled = (wavelen > 8192.0f) ? inv * 0.125f : inv;
    float smooth = (8192.0f / wavelen - 1.0f) * (1.0f / 3.0f);
    float smoothed = (1.0f - smooth) * 0.125f * inv + smooth * inv;
    bool med = (wavelen <= 8192.0f) && (wavelen >= 2048.0f);
    float f = med ? smoothed : inv_scaled;

    float ang = (float)t * f;
    float s = sinf(ang);
    float c = cosf(ang);

    float* p = q + (long)t * (heads * HD) + h * HD;
    float lo = p[i];
    float hi = p[i + 64];
    p[i]      = lo * c - hi * s;
    p[i + 64] = hi * c + lo * s;
}

// ---------------------------------------------------------------------------
// Causal softmax over score rows, with 1/sqrt(D) scale folded in.
// grid = (T, NH), block = 256. Masked entries written as 0 so the dense
// PV GEMM over the full K dimension is exact.
// ---------------------------------------------------------------------------
__global__ void softmax_causal(float* __restrict__ S)
{
    const int i = blockIdx.x;     // query row
    const int h = blockIdx.y;     // head
    float* row = S + ((size_t)h * T_SEQ + i) * T_SEQ;
    const float scale = 0.088388347648318447f;  // 1/sqrt(128)
    const int tid = threadIdx.x;

    __shared__ float red[256];

    float mx = -1e30f;
    for (int j = tid; j <= i; j += 256) mx = fmaxf(mx, row[j] * scale);
    red[tid] = mx;
    __syncthreads();
    for (int s = 128; s > 0; s >>= 1) {
        if (tid < s) red[tid] = fmaxf(red[tid], red[tid + s]);
        __syncthreads();
    }
    mx = red[0];
    __syncthreads();

    float sum = 0.0f;
    for (int j = tid; j <= i; j += 256) {
        float e = __expf(row[j] * scale - mx);
        row[j] = e;
        sum += e;
    }
    red[tid] = sum;
    __syncthreads();
    for (int s = 128; s > 0; s >>= 1) {
        if (tid < s) red[tid] += red[tid + s];
        __syncthreads();
    }
    float rinv = 1.0f / red[0];

    for (int j = tid; j <= i; j += 256) row[j] *= rinv;
    for (int j = i + 1 + tid; j < T_SEQ; j += 256) row[j] = 0.0f;
}

// ---------------------------------------------------------------------------
extern "C" void kernel_launch(void* const* d_in, const int* in_sizes, int n_in,
                              void* d_out, int out_size)
{
    const float* x  = (const float*)d_in[0];
    const float* Wq = (const float*)d_in[1];
    const float* Wk = (const float*)d_in[2];
    const float* Wv = (const float*)d_in[3];
    const float* Wo = (const float*)d_in[4];
    float* out = (float*)d_out;

    float *Q, *K, *V, *S, *O;
    cudaGetSymbolAddress((void**)&Q, g_Q);
    cudaGetSymbolAddress((void**)&K, g_K);
    cudaGetSymbolAddress((void**)&V, g_V);
    cudaGetSymbolAddress((void**)&S, g_S);
    cudaGetSymbolAddress((void**)&O, g_O);

    // QKV projections: C = x * W^T
    gemm128<true><<<dim3(32, 16, 1), 256>>>(x, Wq, Q, T_SEQ, 4096, HID, HID, HID, 4096, 0, 0, 0, 1);
    gemm128<true><<<dim3( 8, 16, 1), 256>>>(x, Wk, K, T_SEQ, 1024, HID, HID, HID, 1024, 0, 0, 0, 1);
    gemm128<true><<<dim3( 8, 16, 1), 256>>>(x, Wv, V, T_SEQ, 1024, HID, HID, HID, 1024, 0, 0, 0, 1);

    // RoPE in place
    rope_kernel<<<dim3(T_SEQ, NH),  64>>>(Q, NH);
    rope_kernel<<<dim3(T_SEQ, NKV), 64>>>(K, NKV);

    // Scores: per head h, S_h = Q_h * K_{h/4}^T  (dense; masked in softmax)
    gemm128<true><<<dim3(16, 16, NH), 256>>>(
        Q, K, S, T_SEQ, T_SEQ, HD,
        /*lda=*/NH * HD, /*ldb=*/NKV * HD, /*ldc=*/T_SEQ,
        /*sA=*/HD, /*sB=*/HD, /*sC=*/(long)T_SEQ * T_SEQ, /*gdiv=*/GRP);

    softmax_causal<<<dim3(T_SEQ, NH), 256>>>(S);

    // O_h = P_h * V_{h/4}
    gemm128<false><<<dim3(1, 16, NH), 256>>>(
        S, V, O, T_SEQ, HD, T_SEQ,
        /*lda=*/T_SEQ, /*ldb=*/NKV * HD, /*ldc=*/NH * HD,
        /*sA=*/(long)T_SEQ * T_SEQ, /*sB=*/HD, /*sC=*/HD, /*gdiv=*/GRP);

    // Output projection: out = O * Wo^T
    gemm128<true><<<dim3(32, 16, 1), 256>>>(O, Wo, out, T_SEQ, HID, 4096, 4096, 4096, HID, 0, 0, 0, 1);
}

// round 2
// speedup vs baseline: 3.4088x; 3.4088x over previous
#include <cuda_runtime.h>
#include <math.h>

#define T_SEQ 2048
#define HID 4096
#define NH 32
#define NKV 8
#define HD 128

// Scratch (allocation-free rule: __device__ globals)
__device__ float g_Q [(size_t)T_SEQ * NH * HD];              // 32 MB  [t][h*128+d]
__device__ float g_K [(size_t)T_SEQ * NKV * HD];             // 8 MB   [t][h*128+d]
__device__ float g_VT[(size_t)NKV * HD * T_SEQ];             // 8 MB   [h][d][t]
__device__ float g_S [(size_t)NH * T_SEQ * T_SEQ];           // 512 MB [h][i][j]
__device__ float g_O [(size_t)T_SEQ * NH * HD];              // 32 MB

__device__ __forceinline__ unsigned f2tf(float f) {
    unsigned u;
    asm("cvt.rna.tf32.f32 %0, %1;" : "=r"(u) : "f"(f));
    return u;
}

// ---------------------------------------------------------------------------
// TF32 tensor-core GEMM: C[M,N] = A[M,K] * B^T, B stored [N,K] row-major.
// Block tile 128x128, K-chunk 32, 256 threads (8 warps, each 64x32 via
// mma.sync.m16n8k8.tf32). Batched via blockIdx.z.
// causal: 0 = none
//         1 = skip blocks with bn > bm (fully-masked upper triangle)
//         2 = cap K at bm+128 (A columns beyond diagonal are zero)
// Requires M,N % 128 == 0, K % 32 == 0.
// ---------------------------------------------------------------------------
__global__ __launch_bounds__(256)
void gemm_tf32(const float* __restrict__ A, const float* __restrict__ B,
               float* __restrict__ C,
               int K, int lda, int ldb, int ldc,
               long sA, long sB, long sC, int gdiv, int causal)
{
    __shared__ unsigned As[128][36];   // [m][k], pad 36 -> conflict-free frag loads
    __shared__ unsigned Bs[128][36];   // [n][k]

    const int bm = blockIdx.y * 128;
    const int bn = blockIdx.x * 128;
    if (causal == 1 && bn > bm) return;

    const int z = blockIdx.z;
    A += (long)z * sA;
    B += (long)(z / gdiv) * sB;
    C += (long)z * sC;

    const int tid  = threadIdx.x;
    const int lane = tid & 31;
    const int w    = tid >> 5;
    const int g    = lane >> 2;        // 0..7
    const int t    = lane & 3;         // 0..3
    const int wm   = (w >> 2) * 64;    // warp M offset in tile
    const int wn   = (w & 3) * 32;     // warp N offset in tile

    float c[4][4][4];
    #pragma unroll
    for (int mi = 0; mi < 4; mi++)
        #pragma unroll
        for (int ni = 0; ni < 4; ni++)
            #pragma unroll
            for (int q = 0; q < 4; q++) c[mi][ni][q] = 0.0f;

    const int kend = (causal == 2) ? (bm + 128 < K ? bm + 128 : K) : K;

    const int lr = tid >> 3;           // 0..31  (row group for loads)
    const int lk = (tid & 7) * 4;      // 0,4,...,28 (k offset for loads)

    for (int k0 = 0; k0 < kend; k0 += 32) {
        #pragma unroll
        for (int p = 0; p < 4; p++) {
            const int r = lr + p * 32;
            float4 a = *reinterpret_cast<const float4*>(A + (long)(bm + r) * lda + k0 + lk);
            uint4 ua = make_uint4(f2tf(a.x), f2tf(a.y), f2tf(a.z), f2tf(a.w));
            *reinterpret_cast<uint4*>(&As[r][lk]) = ua;
            float4 b = *reinterpret_cast<const float4*>(B + (long)(bn + r) * ldb + k0 + lk);
            uint4 ub = make_uint4(f2tf(b.x), f2tf(b.y), f2tf(b.z), f2tf(b.w));
            *reinterpret_cast<uint4*>(&Bs[r][lk]) = ub;
        }
        __syncthreads();

        #pragma unroll
        for (int ks = 0; ks < 32; ks += 8) {
            unsigned af[4][4], bf[4][2];
            #pragma unroll
            for (int mi = 0; mi < 4; mi++) {
                const int r = wm + mi * 16;
                af[mi][0] = As[r + g    ][ks + t    ];
                af[mi][1] = As[r + g + 8][ks + t    ];
                af[mi][2] = As[r + g    ][ks + t + 4];
                af[mi][3] = As[r + g + 8][ks + t + 4];
            }
            #pragma unroll
            for (int ni = 0; ni < 4; ni++) {
                const int cb = wn + ni * 8 + g;
                bf[ni][0] = Bs[cb][ks + t    ];
                bf[ni][1] = Bs[cb][ks + t + 4];
            }
            #pragma unroll
            for (int mi = 0; mi < 4; mi++)
                #pragma unroll
                for (int ni = 0; ni < 4; ni++)
                    asm volatile(
                        "mma.sync.aligned.m16n8k8.row.col.f32.tf32.tf32.f32 "
                        "{%0,%1,%2,%3}, {%4,%5,%6,%7}, {%8,%9}, {%0,%1,%2,%3};"
                        : "+f"(c[mi][ni][0]), "+f"(c[mi][ni][1]),
                          "+f"(c[mi][ni][2]), "+f"(c[mi][ni][3])
                        : "r"(af[mi][0]), "r"(af[mi][1]), "r"(af[mi][2]), "r"(af[mi][3]),
                          "r"(bf[ni][0]), "r"(bf[ni][1]));
        }
        __syncthreads();
    }

    #pragma unroll
    for (int mi = 0; mi < 4; mi++) {
        const int r0 = bm + wm + mi * 16 + g;
        #pragma unroll
        for (int ni = 0; ni < 4; ni++) {
            const int cc = bn + wn + ni * 8 + 2 * t;
            *reinterpret_cast<float2*>(C + (long)r0 * ldc + cc) =
                make_float2(c[mi][ni][0], c[mi][ni][1]);
            *reinterpret_cast<float2*>(C + (long)(r0 + 8) * ldc + cc) =
                make_float2(c[mi][ni][2], c[mi][ni][3]);
        }
    }
}

// ---------------------------------------------------------------------------
// Llama-3 RoPE in place on [T, heads*128]; fp32 math.
// grid = (T, heads/4), block = (64, 4).
// ---------------------------------------------------------------------------
__global__ void rope_kernel(float* __restrict__ q, int heads)
{
    const int t = blockIdx.x;
    const int h = blockIdx.y * 4 + threadIdx.y;
    const int i = threadIdx.x;   // 0..63

    const float e   = (float)i * (1.0f / 64.0f);
    const float inv = exp2f(-18.931568569324174f * e);   // log2(500000)
    const float wavelen = 6.2831853071795865f / inv;
    float f;
    if (wavelen > 8192.0f) {
        f = inv * 0.125f;
    } else if (wavelen < 2048.0f) {
        f = inv;
    } else {
        const float smooth = (8192.0f / wavelen - 1.0f) * (1.0f / 3.0f);
        f = (1.0f - smooth) * 0.125f * inv + smooth * inv;
    }

    float s, c;
    sincosf((float)t * f, &s, &c);

    float* p = q + (long)t * (heads * HD) + h * HD;
    const float lo = p[i];
    const float hi = p[i + 64];
    p[i]      = lo * c - hi * s;
    p[i + 64] = hi * c + lo * s;
}

// ---------------------------------------------------------------------------
// Causal softmax with 1/sqrt(D) scale; masked entries set to 0.
// grid = (T, NH), block = 256.
// ---------------------------------------------------------------------------
__global__ void softmax_causal(float* __restrict__ S)
{
    const int i = blockIdx.x;
    const int h = blockIdx.y;
    float* row = S + ((size_t)h * T_SEQ + i) * T_SEQ;
    const float scale = 0.088388347648318447f;  // 1/sqrt(128)
    const int tid = threadIdx.x;

    __shared__ float red[256];

    float mx = -1e30f;
    for (int j = tid; j <= i; j += 256) mx = fmaxf(mx, row[j] * scale);
    red[tid] = mx;
    __syncthreads();
    for (int s = 128; s > 0; s >>= 1) {
        if (tid < s) red[tid] = fmaxf(red[tid], red[tid + s]);
        __syncthreads();
    }
    mx = red[0];
    __syncthreads();

    float sum = 0.0f;
    for (int j = tid; j <= i; j += 256) {
        float ev = __expf(row[j] * scale - mx);
        row[j] = ev;
        sum += ev;
    }
    red[tid] = sum;
    __syncthreads();
    for (int s = 128; s > 0; s >>= 1) {
        if (tid < s) red[tid] += red[tid + s];
        __syncthreads();
    }
    const float rinv = 1.0f / red[0];

    for (int j = tid; j <= i; j += 256) row[j] *= rinv;
    for (int j = i + 1 + tid; j < T_SEQ; j += 256) row[j] = 0.0f;
}

// ---------------------------------------------------------------------------
extern "C" void kernel_launch(void* const* d_in, const int* in_sizes, int n_in,
                              void* d_out, int out_size)
{
    const float* x  = (const float*)d_in[0];
    const float* Wq = (const float*)d_in[1];
    const float* Wk = (const float*)d_in[2];
    const float* Wv = (const float*)d_in[3];
    const float* Wo = (const float*)d_in[4];
    float* out = (float*)d_out;

    float *Q, *K, *VT, *S, *O;
    cudaGetSymbolAddress((void**)&Q,  g_Q);
    cudaGetSymbolAddress((void**)&K,  g_K);
    cudaGetSymbolAddress((void**)&VT, g_VT);
    cudaGetSymbolAddress((void**)&S,  g_S);
    cudaGetSymbolAddress((void**)&O,  g_O);

    // Q = x * Wq^T   [2048, 4096]
    gemm_tf32<<<dim3(32, 16, 1), 256>>>(x, Wq, Q, HID, HID, HID, 4096, 0, 0, 0, 1, 0);
    // K = x * Wk^T   [2048, 1024]
    gemm_tf32<<<dim3(8, 16, 1), 256>>>(x, Wk, K, HID, HID, HID, 1024, 0, 0, 0, 1, 0);
    // VT = Wv * x^T  [1024, 2048]  (V pre-transposed: VT[h*128+d][t])
    gemm_tf32<<<dim3(16, 8, 1), 256>>>(Wv, x, VT, HID, HID, HID, T_SEQ, 0, 0, 0, 1, 0);

    // RoPE in place
    rope_kernel<<<dim3(T_SEQ, NH  / 4), dim3(64, 4)>>>(Q, NH);
    rope_kernel<<<dim3(T_SEQ, NKV / 4), dim3(64, 4)>>>(K, NKV);

    // Scores: S_h = Q_h * K_{h/4}^T  (skip fully-masked upper blocks)
    gemm_tf32<<<dim3(16, 16, NH), 256>>>(
        Q, K, S, HD,
        /*lda=*/NH * HD, /*ldb=*/NKV * HD, /*ldc=*/T_SEQ,
        /*sA=*/HD, /*sB=*/HD, /*sC=*/(long)T_SEQ * T_SEQ, /*gdiv=*/4, /*causal=*/1);

    softmax_causal<<<dim3(T_SEQ, NH), 256>>>(S);

    // O_h = P_h * V_h  (B = VT_h stored [128, 2048]; K capped at diagonal)
    gemm_tf32<<<dim3(1, 16, NH), 256>>>(
        S, VT, O, T_SEQ,
        /*lda=*/T_SEQ, /*ldb=*/T_SEQ, /*ldc=*/NH * HD,
        /*sA=*/(long)T_SEQ * T_SEQ, /*sB=*/(long)HD * T_SEQ, /*sC=*/HD, /*gdiv=*/4, /*causal=*/2);

    // out = O * Wo^T  [2048, 4096]
    gemm_tf32<<<dim3(32, 16, 1), 256>>>(O, Wo, out, 4096, 4096, 4096, HID, 0, 0, 0, 1, 0);
}

// round 4
// speedup vs baseline: 4.6605x; 1.3672x over previous
#include <cuda_runtime.h>
#include <math.h>

#define T_SEQ 2048
#define HID 4096
#define NH 32
#define NKV 8
#define HD 128
#define FSTR 132   // flash smem row stride (128 + 4 pad, 16B-aligned rows)

// Scratch (allocation-free rule: __device__ globals)
__device__ float g_Q [(size_t)T_SEQ * NH * HD];              // 32 MB [t][h*128+d]
__device__ float g_K [(size_t)T_SEQ * NKV * HD];             // 8 MB  [t][h*128+d]
__device__ float g_VT[(size_t)NKV * HD * T_SEQ];             // 8 MB  [h][d][t]
__device__ float g_O [(size_t)T_SEQ * NH * HD];              // 32 MB

__device__ __forceinline__ unsigned f2tf(float f) {
    unsigned u;
    asm("cvt.rna.tf32.f32 %0, %1;" : "=r"(u) : "f"(f));
    return u;
}

#define MMA_TF32(d, a0,a1,a2,a3, b0,b1)                                       \
    asm volatile(                                                             \
        "mma.sync.aligned.m16n8k8.row.col.f32.tf32.tf32.f32 "                 \
        "{%0,%1,%2,%3}, {%4,%5,%6,%7}, {%8,%9}, {%0,%1,%2,%3};"               \
        : "+f"((d)[0]), "+f"((d)[1]), "+f"((d)[2]), "+f"((d)[3])              \
        : "r"(a0), "r"(a1), "r"(a2), "r"(a3), "r"(b0), "r"(b1))

// ---------------------------------------------------------------------------
// TF32 GEMM: C[M,N] = A[M,K] * B^T, B stored [N,K] row-major.
// Block tile 128x128, K-chunk 32, 256 threads, register-staged prefetch.
// Requires M,N % 128 == 0, K % 32 == 0.
// ---------------------------------------------------------------------------
__global__ __launch_bounds__(256)
void gemm_tf32(const float* __restrict__ A, const float* __restrict__ B,
               float* __restrict__ C, int K, int lda, int ldb, int ldc)
{
    __shared__ unsigned As[128][36];
    __shared__ unsigned Bs[128][36];

    const int bm = blockIdx.y * 128;
    const int bn = blockIdx.x * 128;
    const int tid  = threadIdx.x;
    const int lane = tid & 31;
    const int w    = tid >> 5;
    const int g    = lane >> 2;
    const int t    = lane & 3;
    const int wm   = (w >> 2) * 64;
    const int wn   = (w & 3) * 32;

    float c[4][4][4];
    #pragma unroll
    for (int mi = 0; mi < 4; mi++)
        #pragma unroll
        for (int ni = 0; ni < 4; ni++)
            #pragma unroll
            for (int q = 0; q < 4; q++) c[mi][ni][q] = 0.0f;

    const int lr = tid >> 3;
    const int lk = (tid & 7) * 4;
    const float* Ap = A + (size_t)(bm + lr) * lda + lk;
    const float* Bp = B + (size_t)(bn + lr) * ldb + lk;

    float4 ra[4], rb[4];
    #pragma unroll
    for (int p = 0; p < 4; p++) {
        ra[p] = *reinterpret_cast<const float4*>(Ap + (size_t)(p * 32) * lda);
        rb[p] = *reinterpret_cast<const float4*>(Bp + (size_t)(p * 32) * ldb);
    }

    for (int k0 = 0; k0 < K; k0 += 32) {
        #pragma unroll
        for (int p = 0; p < 4; p++) {
            const int r = lr + p * 32;
            *reinterpret_cast<uint4*>(&As[r][lk]) =
                make_uint4(f2tf(ra[p].x), f2tf(ra[p].y), f2tf(ra[p].z), f2tf(ra[p].w));
            *reinterpret_cast<uint4*>(&Bs[r][lk]) =
                make_uint4(f2tf(rb[p].x), f2tf(rb[p].y), f2tf(rb[p].z), f2tf(rb[p].w));
        }
        __syncthreads();

        if (k0 + 32 < K) {
            Ap += 32; Bp += 32;
            #pragma unroll
            for (int p = 0; p < 4; p++) {
                ra[p] = *reinterpret_cast<const float4*>(Ap + (size_t)(p * 32) * lda);
                rb[p] = *reinterpret_cast<const float4*>(Bp + (size_t)(p * 32) * ldb);
            }
        }

        #pragma unroll
        for (int ks = 0; ks < 32; ks += 8) {
            unsigned af[4][4], bf[4][2];
            #pragma unroll
            for (int mi = 0; mi < 4; mi++) {
                const int r = wm + mi * 16;
                af[mi][0] = As[r + g    ][ks + t    ];
                af[mi][1] = As[r + g + 8][ks + t    ];
                af[mi][2] = As[r + g    ][ks + t + 4];
                af[mi][3] = As[r + g + 8][ks + t + 4];
            }
            #pragma unroll
            for (int ni = 0; ni < 4; ni++) {
                const int cb = wn + ni * 8 + g;
                bf[ni][0] = Bs[cb][ks + t    ];
                bf[ni][1] = Bs[cb][ks + t + 4];
            }
            #pragma unroll
            for (int mi = 0; mi < 4; mi++)
                #pragma unroll
                for (int ni = 0; ni < 4; ni++)
                    MMA_TF32(c[mi][ni], af[mi][0], af[mi][1], af[mi][2], af[mi][3],
                             bf[ni][0], bf[ni][1]);
        }
        __syncthreads();
    }

    #pragma unroll
    for (int mi = 0; mi < 4; mi++) {
        const int r0 = bm + wm + mi * 16 + g;
        #pragma unroll
        for (int ni = 0; ni < 4; ni++) {
            const int cc = bn + wn + ni * 8 + 2 * t;
            *reinterpret_cast<float2*>(C + (size_t)r0 * ldc + cc) =
                make_float2(c[mi][ni][0], c[mi][ni][1]);
            *reinterpret_cast<float2*>(C + (size_t)(r0 + 8) * ldc + cc) =
                make_float2(c[mi][ni][2], c[mi][ni][3]);
        }
    }
}

// ---------------------------------------------------------------------------
// Flash attention: one block per (q-block of 128 rows, head).
// 256 threads, warp w owns rows w*16..w*16+15. Online softmax, TF32 MMAs.
// Q pre-scaled by 1/sqrt(128). Tiles are 128x128 with row stride FSTR=132.
// ---------------------------------------------------------------------------
__global__ __launch_bounds__(256)
void flash_attn(const float* __restrict__ Qg, const float* __restrict__ Kg,
                const float* __restrict__ VTg, float* __restrict__ Og)
{
    extern __shared__ unsigned sm[];
    unsigned* Qs = sm;                   // [128][FSTR]
    unsigned* Ks = sm + 128 * FSTR;      // [128][FSTR]  K tile [tok][d]
    unsigned* Vs = sm + 2 * 128 * FSTR;  // [128][FSTR]  V^T tile [d][tok]

    const int h  = blockIdx.y;
    const int ib = gridDim.x - 1 - blockIdx.x;   // heavy blocks first
    const int kv = h >> 2;
    const int tid  = threadIdx.x;
    const int lane = tid & 31;
    const int w    = tid >> 5;
    const int g    = lane >> 2;
    const int t    = lane & 3;
    const int wr   = w * 16;
    const float scale = 0.088388347648318447f;   // 1/sqrt(128)

    // Load + scale Q tile (rows ib*128.., cols h*128..)
    #pragma unroll
    for (int p = 0; p < 16; p++) {
        const int fidx = tid + 256 * p;
        const int r = fidx >> 5, c4 = (fidx & 31) * 4;
        float4 q = *reinterpret_cast<const float4*>(
            Qg + (size_t)(ib * 128 + r) * (NH * HD) + h * HD + c4);
        unsigned* d = &Qs[r * FSTR + c4];
        d[0] = f2tf(q.x * scale); d[1] = f2tf(q.y * scale);
        d[2] = f2tf(q.z * scale); d[3] = f2tf(q.w * scale);
    }

    float m0 = -1e30f, m1 = -1e30f, l0 = 0.0f, l1 = 0.0f;
    float o[16][4];
    #pragma unroll
    for (int ni = 0; ni < 16; ni++)
        #pragma unroll
        for (int q = 0; q < 4; q++) o[ni][q] = 0.0f;

    for (int j = 0; j <= ib; j++) {
        __syncthreads();   // previous iteration done reading Ks/Vs (also covers Q fill)
        #pragma unroll
        for (int p = 0; p < 16; p++) {
            const int fidx = tid + 256 * p;
            const int r = fidx >> 5, c4 = (fidx & 31) * 4;
            float4 kk = *reinterpret_cast<const float4*>(
                Kg + (size_t)(j * 128 + r) * (NKV * HD) + kv * HD + c4);
            unsigned* dk = &Ks[r * FSTR + c4];
            dk[0] = f2tf(kk.x); dk[1] = f2tf(kk.y); dk[2] = f2tf(kk.z); dk[3] = f2tf(kk.w);
            float4 vv = *reinterpret_cast<const float4*>(
                VTg + ((size_t)kv * HD + r) * T_SEQ + j * 128 + c4);
            unsigned* dv = &Vs[r * FSTR + c4];
            dv[0] = f2tf(vv.x); dv[1] = f2tf(vv.y); dv[2] = f2tf(vv.z); dv[3] = f2tf(vv.w);
        }
        __syncthreads();

        // S = Q * K^T  (16 x 128 per warp)
        float s[16][4];
        #pragma unroll
        for (int ni = 0; ni < 16; ni++)
            #pragma unroll
            for (int q = 0; q < 4; q++) s[ni][q] = 0.0f;

        #pragma unroll
        for (int ks = 0; ks < 16; ks++) {
            const int k8 = ks * 8;
            const unsigned a0 = Qs[(wr + g    ) * FSTR + k8 + t    ];
            const unsigned a1 = Qs[(wr + g + 8) * FSTR + k8 + t    ];
            const unsigned a2 = Qs[(wr + g    ) * FSTR + k8 + t + 4];
            const unsigned a3 = Qs[(wr + g + 8) * FSTR + k8 + t + 4];
            #pragma unroll
            for (int ni = 0; ni < 16; ni++) {
                const unsigned b0 = Ks[(ni * 8 + g) * FSTR + k8 + t    ];
                const unsigned b1 = Ks[(ni * 8 + g) * FSTR + k8 + t + 4];
                MMA_TF32(s[ni], a0, a1, a2, a3, b0, b1);
            }
        }

        // Causal mask on the diagonal block
        if (j == ib) {
            #pragma unroll
            for (int ni = 0; ni < 16; ni++) {
                const int c0 = ni * 8 + 2 * t;
                const int r0 = wr + g, r1 = wr + g + 8;
                if (c0     > r0) s[ni][0] = -1e30f;
                if (c0 + 1 > r0) s[ni][1] = -1e30f;
                if (c0     > r1) s[ni][2] = -1e30f;
                if (c0 + 1 > r1) s[ni][3] = -1e30f;
            }
        }

        // Online softmax update
        float bm0 = -1e30f, bm1 = -1e30f;
        #pragma unroll
        for (int ni = 0; ni < 16; ni++) {
            bm0 = fmaxf(bm0, fmaxf(s[ni][0], s[ni][1]));
            bm1 = fmaxf(bm1, fmaxf(s[ni][2], s[ni][3]));
        }
        bm0 = fmaxf(bm0, __shfl_xor_sync(0xffffffffu, bm0, 1));
        bm0 = fmaxf(bm0, __shfl_xor_sync(0xffffffffu, bm0, 2));
        bm1 = fmaxf(bm1, __shfl_xor_sync(0xffffffffu, bm1, 1));
        bm1 = fmaxf(bm1, __shfl_xor_sync(0xffffffffu, bm1, 2));

        const float mn0 = fmaxf(m0, bm0), mn1 = fmaxf(m1, bm1);
        const float al0 = __expf(m0 - mn0), al1 = __expf(m1 - mn1);
        m0 = mn0; m1 = mn1;

        float rs0 = 0.0f, rs1 = 0.0f;
        #pragma unroll
        for (int ni = 0; ni < 16; ni++) {
            s[ni][0] = __expf(s[ni][0] - mn0);
            s[ni][1] = __expf(s[ni][1] - mn0);
            s[ni][2] = __expf(s[ni][2] - mn1);
            s[ni][3] = __expf(s[ni][3] - mn1);
            rs0 += s[ni][0] + s[ni][1];
            rs1 += s[ni][2] + s[ni][3];
        }
        rs0 += __shfl_xor_sync(0xffffffffu, rs0, 1);
        rs0 += __shfl_xor_sync(0xffffffffu, rs0, 2);
        rs1 += __shfl_xor_sync(0xffffffffu, rs1, 1);
        rs1 += __shfl_xor_sync(0xffffffffu, rs1, 2);
        l0 = l0 * al0 + rs0;
        l1 = l1 * al1 + rs1;

        #pragma unroll
        for (int ni = 0; ni < 16; ni++) {
            o[ni][0] *= al0; o[ni][1] *= al0;
            o[ni][2] *= al1; o[ni][3] *= al1;
        }

        // Convert P to tf32 bit patterns in the acc registers
        #pragma unroll
        for (int ni = 0; ni < 16; ni++)
            #pragma unroll
            for (int q = 0; q < 4; q++)
                s[ni][q] = __uint_as_float(f2tf(s[ni][q]));

        // O += P * V   (A-frags for P come from acc regs via quad shuffles)
        const int base = (lane & ~3) | (t >> 1);
        const bool odd = (t & 1);
        #pragma unroll
        for (int kt = 0; kt < 16; kt++) {
            const float v0 = __shfl_sync(0xffffffffu, s[kt][0], base);
            const float v1 = __shfl_sync(0xffffffffu, s[kt][1], base);
            const float v2 = __shfl_sync(0xffffffffu, s[kt][2], base);
            const float v3 = __shfl_sync(0xffffffffu, s[kt][3], base);
            const float u0 = __shfl_sync(0xffffffffu, s[kt][0], base + 2);
            const float u1 = __shfl_sync(0xffffffffu, s[kt][1], base + 2);
            const float u2 = __shfl_sync(0xffffffffu, s[kt][2], base + 2);
            const float u3 = __shfl_sync(0xffffffffu, s[kt][3], base + 2);
            const unsigned a0 = __float_as_uint(odd ? v1 : v0);
            const unsigned a1 = __float_as_uint(odd ? v3 : v2);
            const unsigned a2 = __float_as_uint(odd ? u1 : u0);
            const unsigned a3 = __float_as_uint(odd ? u3 : u2);
            const int k8 = kt * 8;
            #pragma unroll
            for (int ni = 0; ni < 16; ni++) {
                const unsigned b0 = Vs[(ni * 8 + g) * FSTR + k8 + t    ];
                const unsigned b1 = Vs[(ni * 8 + g) * FSTR + k8 + t + 4];
                MMA_TF32(o[ni], a0, a1, a2, a3, b0, b1);
            }
        }
    }

    // Epilogue: normalize and store
    const float i0 = 1.0f / l0, i1 = 1.0f / l1;
    const size_t r0 = (size_t)(ib * 128 + wr + g) * (NH * HD) + h * HD;
    const size_t r1 = r0 + (size_t)8 * (NH * HD);
    #pragma unroll
    for (int ni = 0; ni < 16; ni++) {
        const int cc = ni * 8 + 2 * t;
        *reinterpret_cast<float2*>(Og + r0 + cc) = make_float2(o[ni][0] * i0, o[ni][1] * i0);
        *reinterpret_cast<float2*>(Og + r1 + cc) = make_float2(o[ni][2] * i1, o[ni][3] * i1);
    }
}

// ---------------------------------------------------------------------------
// Llama-3 RoPE in place on [T, heads*128]; fp32 math.
// ---------------------------------------------------------------------------
__global__ void rope_kernel(float* __restrict__ q, int heads)
{
    const int t = blockIdx.x;
    const int h = blockIdx.y * 4 + threadIdx.y;
    const int i = threadIdx.x;   // 0..63

    const float e   = (float)i * (1.0f / 64.0f);
    const float inv = exp2f(-18.931568569324174f * e);   // log2(500000)
    const float wavelen = 6.2831853071795865f / inv;
    float f;
    if (wavelen > 8192.0f) {
        f = inv * 0.125f;
    } else if (wavelen < 2048.0f) {
        f = inv;
    } else {
        const float smooth = (8192.0f / wavelen - 1.0f) * (1.0f / 3.0f);
        f = (1.0f - smooth) * 0.125f * inv + smooth * inv;
    }

    float s, c;
    sincosf((float)t * f, &s, &c);

    float* p = q + (size_t)t * (heads * HD) + h * HD;
    const float lo = p[i];
    const float hi = p[i + 64];
    p[i]      = lo * c - hi * s;
    p[i + 64] = hi * c + lo * s;
}

// ---------------------------------------------------------------------------
extern "C" void kernel_launch(void* const* d_in, const int* in_sizes, int n_in,
                              void* d_out, int out_size)
{
    const float* x  = (const float*)d_in[0];
    const float* Wq = (const float*)d_in[1];
    const float* Wk = (const float*)d_in[2];
    const float* Wv = (const float*)d_in[3];
    const float* Wo = (const float*)d_in[4];
    float* out = (float*)d_out;

    float *Q, *K, *VT, *O;
    cudaGetSymbolAddress((void**)&Q,  g_Q);
    cudaGetSymbolAddress((void**)&K,  g_K);
    cudaGetSymbolAddress((void**)&VT, g_VT);
    cudaGetSymbolAddress((void**)&O,  g_O);

    // Projections (all C = A * B^T)
    gemm_tf32<<<dim3(32, 16), 256>>>(x,  Wq, Q,  HID, HID, HID, 4096);
    gemm_tf32<<<dim3( 8, 16), 256>>>(x,  Wk, K,  HID, HID, HID, 1024);
    gemm_tf32<<<dim3(16,  8), 256>>>(Wv, x,  VT, HID, HID, HID, T_SEQ);

    // RoPE in place
    rope_kernel<<<dim3(T_SEQ, NH  / 4), dim3(64, 4)>>>(Q, NH);
    rope_kernel<<<dim3(T_SEQ, NKV / 4), dim3(64, 4)>>>(K, NKV);

    // Fused causal attention
    const int flash_smem = 3 * 128 * FSTR * 4;   // 202752 B
    cudaFuncSetAttribute(flash_attn, cudaFuncAttributeMaxDynamicSharedMemorySize, flash_smem);
    flash_attn<<<dim3(16, NH), 256, flash_smem>>>(Q, K, VT, O);

    // Output projection
    gemm_tf32<<<dim3(32, 16), 256>>>(O, Wo, out, 4096, 4096, 4096, HID);
}